// round 16
// baseline (speedup 1.0000x reference)
#include <cuda_runtime.h>
#include <string.h>
#include <math.h>

#define NQ 14
#define NL 4
#define NGATES 56
#define MB 4

typedef unsigned long long u64;

// Param-only bucket tables S_m(t).
__device__ float2 g_S[14 * 8192];

struct SetupCfg {
    unsigned long long WA[NQ][128];
    unsigned long long WB[NQ][64];
    unsigned char gl[NQ][56];
    unsigned char vmask[NQ][8];
    unsigned char nch[NQ];
    unsigned char nfl[NQ];
    int soff[NQ];
};

struct MainCfg {
    unsigned char keff[NQ], klo[NQ], khi[NQ], jtop[NQ];
    unsigned char jb[NQ][NQ];
    int soff[NQ];
    unsigned char mlist[2][8];   // qubit sets per y-block
    unsigned char nm[2];
};

__device__ __forceinline__ float2 cmulf(float2 a, float2 b) {
    return make_float2(a.x * b.x - a.y * b.y, a.x * b.y + a.y * b.x);
}
__device__ __forceinline__ u64 pk2(float lo, float hi) {
    u64 r; asm("mov.b64 %0,{%1,%2};" : "=l"(r) : "f"(lo), "f"(hi)); return r;
}
__device__ __forceinline__ void upk2(u64 v, float& lo, float& hi) {
    asm("mov.b64 {%0,%1},%2;" : "=f"(lo), "=f"(hi) : "l"(v));
}
__device__ __forceinline__ u64 fma2(u64 a, u64 b, u64 c) {
    u64 d; asm("fma.rn.f32x2 %0,%1,%2,%3;" : "=l"(d) : "l"(a), "l"(b), "l"(c)); return d;
}

__global__ void __launch_bounds__(256)
qzero(int n)
{
    int i = blockIdx.x * 256 + threadIdx.x;
    if (i < n) g_S[i] = make_float2(0.f, 0.f);
}

// grid (32, NQ), block 256: one thread per (t, f) pair. Validated R12/R14.
__global__ void __launch_bounds__(256)
qsetup(const float* __restrict__ params, SetupCfg c)
{
    __shared__ unsigned long long WA[128], WB[64];
    __shared__ float TD[8 * 128];
    __shared__ float th[NGATES];
    __shared__ float thetaTot;
    __shared__ float2 part[8];

    const int m = blockIdx.y, tid = threadIdx.x;
    if (tid < NGATES) th[tid] = params[tid];
    if (tid < 128) WA[tid] = c.WA[m][tid];
    if (tid >= 128 && tid < 192) WB[tid - 128] = c.WB[m][tid - 128];
    __syncthreads();

    for (int e = tid; e < 1024; e += 256) {
        const int ch = e >> 7, idx = e & 127;
        float s = 0.f;
        #pragma unroll
        for (int r = 0; r < 7; ++r) {
            unsigned char g = c.gl[m][ch * 7 + r];
            if (((idx >> r) & 1) && g != 0xFF) s += th[g];
        }
        TD[e] = s;
    }
    __syncthreads();
    if (tid == 0) {
        float s = 0.f;
        for (int ch = 0; ch < c.nch[m]; ++ch) s += TD[ch * 128 + c.vmask[m][ch]];
        thetaTot = s;
    }
    __syncthreads();

    const int nfl = c.nfl[m], nf = 1 << nfl;
    const int pair = blockIdx.x * 256 + tid;
    unsigned long long w = WA[pair & 127] ^ WB[pair >> 7];
    float dot = 0.f;
    const int nch = c.nch[m];
    for (int ch = 0; ch < nch; ++ch)
        dot += TD[ch * 128 + (int)((w >> (7 * ch)) & 127ull)];
    const float ang = thetaTot - 2.f * dot;
    float2 v;
    sincosf(ang, &v.y, &v.x);

    const int f  = tid & (nf - 1);
    const int wl = nf < 32 ? nf : 32;
    for (int o = 1; o < wl; o <<= 1) {
        v.x += __shfl_xor_sync(0xffffffffu, v.x, o);
        v.y += __shfl_xor_sync(0xffffffffu, v.y, o);
    }
    if (nf <= 32) {
        if (f == 0) g_S[c.soff[m] + (pair >> nfl)] = v;
    } else {
        if ((tid & 31) == 0) part[tid >> 5] = v;
        __syncthreads();
        if (nf <= 256) {
            const int bpb = 256 / nf, wps = nf / 32;
            if (tid < bpb) {
                float2 s = make_float2(0.f, 0.f);
                for (int ww = 0; ww < wps; ++ww) {
                    s.x += part[tid * wps + ww].x;
                    s.y += part[tid * wps + ww].y;
                }
                g_S[c.soff[m] + ((blockIdx.x * 256) >> nfl) + tid] = s;
            }
        } else {
            if (tid == 0) {
                float2 s = make_float2(0.f, 0.f);
                for (int ww = 0; ww < 8; ++ww) { s.x += part[ww].x; s.y += part[ww].y; }
                atomicAdd(&g_S[c.soff[m] + ((blockIdx.x * 256) >> nfl)].x, s.x);
                atomicAdd(&g_S[c.soff[m] + ((blockIdx.x * 256) >> nfl)].y, s.y);
            }
        }
    }
}

// grid (batch/MB, 2): y selects a balanced half of the 14 contractions.
__global__ void __launch_bounds__(256)
qmain(const float* __restrict__ x, float* __restrict__ out, int batch, MainCfg c)
{
    __shared__ float2 u[MB][NQ];
    __shared__ float4 PA[8][16][2];    // [mi][e][half]: batches {0,1} / {2,3}
    __shared__ float4 PB[8][16][2];
    __shared__ float4 PHP[8][4][MB];   // packed (hx,hx,-hy,hy) per batch
    __shared__ float red[8][8][MB];

    const int tid = threadIdx.x;
    const int set = blockIdx.y;
    const int nm  = c.nm[set];
    const int bbase = blockIdx.x * MB;

    if (tid < MB * NQ) {
        int b = tid / NQ, j = tid % NQ;
        int bb = bbase + b; if (bb >= batch) bb = batch - 1;
        float s, co;
        sincosf(x[bb * NQ + (13 - j)], &s, &co);   // u[j] = e^{i x_{13-j}}
        u[b][j] = make_float2(co, s);
    }
    __syncthreads();

    // build PA/PB/PHP for this set's qubits: nm * (64 + 64 + 16) slots
    for (int E = tid; E < nm * 144; E += 256) {
        const int mi = E / 144, s = E - mi * 144;
        const int m  = c.mlist[set][mi];
        const int klo = c.klo[m];
        float2 v;
        if (s < 64) {
            const int e = s >> 2, b = s & 3;
            v = make_float2(1.f, 0.f);
            const int nb = klo < 4 ? klo : 4;
            for (int r = 0; r < nb; ++r) {
                float2 w = u[b][c.jb[m][r]];
                if ((e >> r) & 1) w.y = -w.y;
                v = cmulf(v, w);
            }
            *(reinterpret_cast<float2*>(&PA[mi][e][0]) + b) = v;
        } else if (s < 128) {
            const int e = (s - 64) >> 2, b = (s - 64) & 3;
            v = make_float2(1.f, 0.f);
            const int nb = klo > 4 ? klo - 4 : 0;
            for (int r = 0; r < nb; ++r) {
                float2 w = u[b][c.jb[m][4 + r]];
                if ((e >> r) & 1) w.y = -w.y;
                v = cmulf(v, w);
            }
            *(reinterpret_cast<float2*>(&PB[mi][e][0]) + b) = v;
        } else {
            const int e = (s - 128) >> 2, b = (s - 128) & 3;
            v = u[b][c.jtop[m]];          // fixed top delta bit contributes +x
            const int nb = c.khi[m];
            for (int r = 0; r < nb; ++r) {
                float2 w = u[b][c.jb[m][klo + r]];
                if ((e >> r) & 1) w.y = -w.y;
                v = cmulf(v, w);
            }
            PHP[mi][e][b] = make_float4(v.x, v.x, -v.y, v.y);
        }
    }
    __syncthreads();

    const int warp = tid >> 5, lane = tid & 31;
    #pragma unroll 1
    for (int mi = 0; mi < nm; ++mi) {
        const int m   = c.mlist[set][mi];
        const int klo = c.klo[m];
        const int lomask = (1 << klo) - 1;
        const int nt = 1 << c.keff[m];
        const int so = c.soff[m];

        const float4 a0 = PA[mi][tid & 15][0],            a1 = PA[mi][tid & 15][1];
        const float4 b0 = PB[mi][(tid & lomask) >> 4][0], b1 = PB[mi][(tid & lomask) >> 4][1];
        const float2 pl0 = cmulf(make_float2(a0.x, a0.y), make_float2(b0.x, b0.y));
        const float2 pl1 = cmulf(make_float2(a0.z, a0.w), make_float2(b0.z, b0.w));
        const float2 pl2 = cmulf(make_float2(a1.x, a1.y), make_float2(b1.x, b1.y));
        const float2 pl3 = cmulf(make_float2(a1.z, a1.w), make_float2(b1.z, b1.w));

        u64 ac0 = pk2(0.f, 0.f), ac1 = ac0, ac2 = ac0, ac3 = ac0;
        for (int t = tid; t < nt; t += 256) {
            const float2 S = __ldg(&g_S[so + t]);
            const u64 Sxy = pk2(S.x, S.y);
            const u64 Syx = pk2(S.y, S.x);
            const int e = t >> klo;                // warp-uniform
            const float4 h0 = PHP[mi][e][0];
            const float4 h1 = PHP[mi][e][1];
            const float4 h2 = PHP[mi][e][2];
            const float4 h3 = PHP[mi][e][3];
            ac0 = fma2(pk2(h0.x, h0.y), Sxy, ac0);
            ac0 = fma2(pk2(h0.z, h0.w), Syx, ac0);
            ac1 = fma2(pk2(h1.x, h1.y), Sxy, ac1);
            ac1 = fma2(pk2(h1.z, h1.w), Syx, ac1);
            ac2 = fma2(pk2(h2.x, h2.y), Sxy, ac2);
            ac2 = fma2(pk2(h2.z, h2.w), Syx, ac2);
            ac3 = fma2(pk2(h3.x, h3.y), Sxy, ac3);
            ac3 = fma2(pk2(h3.z, h3.w), Syx, ac3);
        }
        float ax, ay;
        upk2(ac0, ax, ay); float r0 = pl0.x * ax - pl0.y * ay;
        upk2(ac1, ax, ay); float r1 = pl1.x * ax - pl1.y * ay;
        upk2(ac2, ax, ay); float r2 = pl2.x * ax - pl2.y * ay;
        upk2(ac3, ax, ay); float r3 = pl3.x * ax - pl3.y * ay;
        #pragma unroll
        for (int o = 16; o; o >>= 1) {
            r0 += __shfl_down_sync(0xffffffffu, r0, o);
            r1 += __shfl_down_sync(0xffffffffu, r1, o);
            r2 += __shfl_down_sync(0xffffffffu, r2, o);
            r3 += __shfl_down_sync(0xffffffffu, r3, o);
        }
        if (lane == 0) {
            red[warp][mi][0] = r0; red[warp][mi][1] = r1;
            red[warp][mi][2] = r2; red[warp][mi][3] = r3;
        }
    }
    __syncthreads();
    if (tid < nm * MB) {
        const int mi = tid >> 2, b = tid & 3;
        const int m  = c.mlist[set][mi];
        float s = 0.f;
        #pragma unroll
        for (int w2 = 0; w2 < 8; ++w2) s += red[w2][mi][b];
        const int bb = bbase + b;
        if (bb < batch) out[bb * NQ + (13 - m)] = s * (1.f / 8192.f);
    }
}

// ================= host side (mask math identical to validated R8-R14) =================
static unsigned Pp(unsigned v, int q) {
    int cc = 13 - ((q + 1) % NQ);
    int tt = 13 - q;
    return v ^ (((v >> cc) & 1u) << tt);
}
static unsigned C1(unsigned v)  { for (int q = 0;      q < NQ; ++q) v = Pp(v, q); return v; }
static unsigned C1i(unsigned v) { for (int q = NQ - 1; q >= 0; --q) v = Pp(v, q); return v; }

extern "C" void kernel_launch(void* const* d_in, const int* in_sizes, int n_in,
                              void* d_out, int out_size)
{
    static SetupCfg sc;
    static MainCfg  mc;
    memset(&sc, 0, sizeof(sc));
    memset(&mc, 0, sizeof(mc));

    unsigned mu[NGATES];
    for (int l = 0; l < NL; ++l) {
        unsigned col[NQ];
        for (int j = 0; j < NQ; ++j) {
            unsigned v = 1u << j;
            for (int r = 0; r < l; ++r) v = C1(v);
            col[j] = v;
        }
        for (int q = 0; q < NQ; ++q) {
            unsigned mask = 0;
            for (int j = 0; j < NQ; ++j) mask |= ((col[j] >> (13 - q)) & 1u) << j;
            mu[l * NQ + q] = mask;
        }
    }

    int soff = 0, need_zero = 0;
    int keffv[NQ];
    for (int m = 0; m < NQ; ++m) {
        unsigned dl = 1u << m;
        for (int r = 0; r < NL; ++r) dl = C1i(dl);
        const int k = __builtin_popcount(dl);
        unsigned char dbits[NQ], cbits[NQ];
        int nd = 0, nc2 = 0;
        for (int bb = 0; bb < NQ; ++bb) {
            if ((dl >> bb) & 1) dbits[nd++] = (unsigned char)bb;
            else                cbits[nc2++] = (unsigned char)bb;
        }
        int ngl = 0;
        unsigned char glist[NGATES];
        for (int g = 0; g < NGATES; ++g)
            if (__builtin_popcount(mu[g] & dl) & 1) glist[ngl++] = (unsigned char)g;
        memset(sc.gl[m], 0xFF, 56);
        for (int r = 0; r < ngl; ++r) sc.gl[m][r] = glist[r];
        const int nch = (ngl + 6) / 7;
        sc.nch[m] = (unsigned char)nch;
        for (int ch = 0; ch < nch; ++ch) {
            int nv = ngl - 7 * ch; if (nv > 7) nv = 7;
            sc.vmask[m][ch] = (unsigned char)((1 << nv) - 1);
        }
        const int keff = k - 1, nfl = 14 - k;
        sc.nfl[m] = (unsigned char)nfl;
        if (nfl > 8) need_zero = 1;
        auto pair2p = [&](unsigned pr) {
            unsigned p = 0;
            for (int r = 0; r < nfl;  ++r) if ((pr >> r) & 1)         p |= 1u << cbits[r];
            for (int r = 0; r < keff; ++r) if ((pr >> (nfl + r)) & 1) p |= 1u << dbits[r];
            return p;
        };
        auto sigw = [&](unsigned p) {
            unsigned long long w = 0;
            for (int r = 0; r < ngl; ++r)
                if (__builtin_popcount(p & mu[glist[r]]) & 1) w |= 1ull << r;
            return w;
        };
        for (int a = 0; a < 128; ++a) sc.WA[m][a] = sigw(pair2p((unsigned)a));
        for (int h = 0; h < 64;  ++h) sc.WB[m][h] = sigw(pair2p(((unsigned)h) << 7));

        int klo = keff < 8 ? keff : 8;
        int khi = keff - klo;
        if (khi > 2) { klo = keff - 2; khi = 2; }   // PHP holds 4 entries
        mc.keff[m] = (unsigned char)keff;
        mc.klo[m]  = (unsigned char)klo;
        mc.khi[m]  = (unsigned char)khi;
        mc.jtop[m] = dbits[k - 1];
        for (int r = 0; r < keff; ++r) mc.jb[m][r] = dbits[r];
        sc.soff[m] = mc.soff[m] = soff;
        soff += 1 << keff;
        keffv[m] = keff;
    }

    // balanced 2-way partition of qubits by 2^keff (greedy, descending)
    {
        int ord[NQ];
        for (int i = 0; i < NQ; ++i) ord[i] = i;
        for (int i = 0; i < NQ; ++i)
            for (int j = i + 1; j < NQ; ++j)
                if (keffv[ord[j]] > keffv[ord[i]]) { int t = ord[i]; ord[i] = ord[j]; ord[j] = t; }
        long w0 = 0, w1 = 0;
        int n0 = 0, n1 = 0;
        for (int i = 0; i < NQ; ++i) {
            int m = ord[i];
            long wm = 1L << keffv[m];
            if ((w0 <= w1 && n0 < 8) || n1 >= 8) { mc.mlist[0][n0++] = (unsigned char)m; w0 += wm; }
            else                                  { mc.mlist[1][n1++] = (unsigned char)m; w1 += wm; }
        }
        mc.nm[0] = (unsigned char)n0;
        mc.nm[1] = (unsigned char)n1;
    }

    const float* x      = (const float*)d_in[0];
    const float* params = (const float*)d_in[1];
    const int    batch  = in_sizes[0] / NQ;

    if (need_zero) qzero<<<(soff + 255) / 256, 256>>>(soff);
    qsetup<<<dim3(32, NQ), 256>>>(params, sc);
    qmain<<<dim3((batch + MB - 1) / MB, 2), 256>>>(x, (float*)d_out, batch, mc);
}